// round 7
// baseline (speedup 1.0000x reference)
#include <cuda_runtime.h>
#include <math.h>
#include <float.h>

#define BATCH 16
#define NPTS  2048
#define DIM   64
#define SPLIT 16
#define ROWS_PER (NPTS / SPLIT)   // 128
#define STR 68                    // row stride: 16B-aligned rows
#define ETHREADS 256

#define EIG_SMEM_FLOATS (4 * DIM * STR)
#define EIG_SMEM_BYTES  (EIG_SMEM_FLOATS * 4)

// scratch for partial maxima: 16 * 16 * 4096 * 4B = 4 MB
__device__ float g_partial[BATCH][SPLIT][DIM * DIM];

// ---------------------------------------------------------------------------
// Kernel 1: partial max of outer products over a 128-row chunk of n
// ---------------------------------------------------------------------------
__global__ void __launch_bounds__(256) sop_partial_max(const float* __restrict__ x) {
    const int b = blockIdx.y;
    const int c = blockIdx.x;
    __shared__ float xs[ROWS_PER][DIM];

    const float* xp = x + ((size_t)b * NPTS + (size_t)c * ROWS_PER) * DIM;
    const int tid = threadIdx.x;

    for (int e = tid * 4; e < ROWS_PER * DIM; e += 256 * 4) {
        float4 v = *(const float4*)(xp + e);
        *(float4*)(&xs[0][0] + e) = v;
    }
    __syncthreads();

    const int ti = (tid >> 4) * 4;
    const int tj = (tid & 15) * 4;
    float acc[4][4];
#pragma unroll
    for (int a = 0; a < 4; a++)
#pragma unroll
        for (int bb = 0; bb < 4; bb++) acc[a][bb] = -FLT_MAX;

#pragma unroll 4
    for (int n = 0; n < ROWS_PER; n++) {
        float4 vi = *(const float4*)&xs[n][ti];
        float4 vj = *(const float4*)&xs[n][tj];
        float fi[4] = {vi.x, vi.y, vi.z, vi.w};
        float fj[4] = {vj.x, vj.y, vj.z, vj.w};
#pragma unroll
        for (int a = 0; a < 4; a++)
#pragma unroll
            for (int bb = 0; bb < 4; bb++)
                acc[a][bb] = fmaxf(acc[a][bb], fi[a] * fj[bb]);
    }

    float* outp = g_partial[b][c];
#pragma unroll
    for (int a = 0; a < 4; a++) {
        float4 v = make_float4(acc[a][0], acc[a][1], acc[a][2], acc[a][3]);
        *(float4*)(outp + (ti + a) * DIM + tj) = v;
    }
}

// ---------------------------------------------------------------------------
// block reduce sum for 256 threads / 8 warps
// ---------------------------------------------------------------------------
__device__ __forceinline__ float block_reduce_sum(float v, float* red, int tid) {
    __syncthreads();
#pragma unroll
    for (int o = 16; o; o >>= 1) v += __shfl_down_sync(0xffffffffu, v, o);
    if ((tid & 31) == 0) red[tid >> 5] = v;
    __syncthreads();
    if (tid < 32) {
        float w = (tid < 8) ? red[tid] : 0.f;
#pragma unroll
        for (int o = 4; o; o >>= 1) w += __shfl_down_sync(0xffffffffu, w, o);
        if (tid == 0) red[0] = w;
    }
    __syncthreads();
    return red[0];
}

// ---------------------------------------------------------------------------
// Kernel 2: 4 Jacobi sweeps (+valve 5th), then 2nd-order Daleckii-Krein
// matrix sqrt + Qt^T F2 Qt reconstruction + L2 normalize.
// 256 threads / 8 warps. Warp w owns row-pairs {w, w+8, w+16, w+24};
// lane j owns column pair j. Qt update: quarter-warp x 2*float4.
// ---------------------------------------------------------------------------
__global__ void __launch_bounds__(ETHREADS) sop_eig_kernel(float* __restrict__ out) {
    extern __shared__ float dsm[];
    float* Abuf0 = dsm;
    float* Abuf1 = dsm + DIM * STR;
    float* Qts   = dsm + 2 * DIM * STR;
    float* Gbuf  = dsm + 3 * DIM * STR;

    __shared__ float red[8];
    __shared__ float gs[DIM];
    __shared__ float dsv[DIM];

    const int b = blockIdx.x;
    const int tid = threadIdx.x;
    const int warp = tid >> 5;
    const int lane = tid & 31;

    // ---- reduce partials into A0, init Qt = I (thread: row i, 16 cols) ----
    float frloc = 0.f;
    {
        const int i = tid >> 2;
        const int j0 = (tid & 3) * 16;
        float4 m[4];
#pragma unroll
        for (int t = 0; t < 4; t++)
            m[t] = make_float4(-FLT_MAX, -FLT_MAX, -FLT_MAX, -FLT_MAX);
#pragma unroll
        for (int c = 0; c < SPLIT; c++) {
            const float4* gp = (const float4*)&g_partial[b][c][i * DIM + j0];
#pragma unroll
            for (int t = 0; t < 4; t++) {
                float4 v = gp[t];
                m[t].x = fmaxf(m[t].x, v.x); m[t].y = fmaxf(m[t].y, v.y);
                m[t].z = fmaxf(m[t].z, v.z); m[t].w = fmaxf(m[t].w, v.w);
            }
        }
#pragma unroll
        for (int t = 0; t < 4; t++) {
            *(float4*)&Abuf0[i * STR + j0 + 4 * t] = m[t];
            frloc += m[t].x*m[t].x + m[t].y*m[t].y + m[t].z*m[t].z + m[t].w*m[t].w;
            float4 id = make_float4((i == j0+4*t+0)?1.f:0.f, (i == j0+4*t+1)?1.f:0.f,
                                    (i == j0+4*t+2)?1.f:0.f, (i == j0+4*t+3)?1.f:0.f);
            *(float4*)&Qts[i * STR + j0 + 4 * t] = id;
        }
    }
    const float frob2 = block_reduce_sum(frloc, red, tid) + 1e-30f;

    // ---- persistent tournament indices for this lane's column pair ----
    int pl, ql;
    if (lane == 0) { pl = 63; ql = 0; }
    else           { pl = lane; ql = 63 - lane; }
    int plS = pl * STR;
    int qlS = ql * STR;

    float* Ac = Abuf0;
    float* An = Abuf1;

    for (int sweep = 0; sweep < 5; sweep++) {
        if (sweep == 4) {   // valve: 5th sweep only if off-diag mass too big for DK
            float off = 0.f;
            const int i = tid >> 2;
            const int j0 = (tid & 3) * 16;
#pragma unroll
            for (int u = 0; u < 16; u++) {
                const float v = Ac[i * STR + j0 + u];
                off += (i != j0 + u) ? v * v : 0.f;
            }
            const float offt = block_reduce_sum(off, red, tid);
            if (offt < 3e-5f * frob2) break;
        }

        for (int r = 0; r < 63; r++) {
            // ---- rotation params for column pair 'lane' (2 MUFU) ----
            const float app = Ac[plS + pl];
            const float aqq = Ac[qlS + ql];
            const float apq = Ac[plS + ql];
            const float d = aqq - app;
            const float g = apq + apq;
            const float rr = fmaf(d, d, g * g);
            const float ir = __frsqrt_rn(rr);
            const float xv = fabsf(d) * ir;
            const float yv = fmaf(0.5f, xv, 0.5f);
            const float ic = __frsqrt_rn(yv);
            float c = yv * ic;
            float s = 0.5f * g * ir * ic;
            s = __int_as_float(__float_as_int(s) ^
                               (__float_as_int(d) & 0x80000000));
            if (rr < 1e-40f) { c = 1.f; s = 0.f; }

            // ---- params for the 4 row-pairs of this warp ----
            float cR[4], sR[4]; int pR[4], qR[4];
#pragma unroll
            for (int u = 0; u < 4; u++) {
                const int src = warp + 8 * u;
                cR[u] = __shfl_sync(0xffffffffu, c,   src);
                sR[u] = __shfl_sync(0xffffffffu, s,   src);
                pR[u] = __shfl_sync(0xffffffffu, plS, src);
                qR[u] = __shfl_sync(0xffffffffu, qlS, src);
            }

            // ---- A: fused two-sided 2x2 updates, 4 row-pairs ----
#pragma unroll
            for (int u = 0; u < 4; u++) {
                const float a_pp = Ac[pR[u] + pl];
                const float a_pq = Ac[pR[u] + ql];
                const float a_qp = Ac[qR[u] + pl];
                const float a_qq = Ac[qR[u] + ql];
                const float rp_p = fmaf(cR[u], a_pp, -sR[u] * a_qp);
                const float rp_q = fmaf(cR[u], a_pq, -sR[u] * a_qq);
                const float rq_p = fmaf(sR[u], a_pp,  cR[u] * a_qp);
                const float rq_q = fmaf(sR[u], a_pq,  cR[u] * a_qq);
                An[pR[u] + pl] = fmaf(c, rp_p, -s * rp_q);
                An[pR[u] + ql] = fmaf(s, rp_p,  c * rp_q);
                An[qR[u] + pl] = fmaf(c, rq_p, -s * rq_q);
                An[qR[u] + ql] = fmaf(s, rq_p,  c * rq_q);
            }

            // ---- Qt <- J^T Qt: quarter-warp, 2x float4 per row ----
            {
                const int rpq = warp + 8 * (lane >> 3);
                const float cq = __shfl_sync(0xffffffffu, c,   rpq);
                const float sq = __shfl_sync(0xffffffffu, s,   rpq);
                const int   pS = __shfl_sync(0xffffffffu, plS, rpq);
                const int   qS = __shfl_sync(0xffffffffu, qlS, rpq);
                const int   sub = (lane & 7) * 8;
                float4* Qp = (float4*)(Qts + pS + sub);
                float4* Qq = (float4*)(Qts + qS + sub);
                const float4 p0 = Qp[0], p1 = Qp[1];
                const float4 q0 = Qq[0], q1 = Qq[1];
                Qp[0] = make_float4(fmaf(cq, p0.x, -sq * q0.x),
                                    fmaf(cq, p0.y, -sq * q0.y),
                                    fmaf(cq, p0.z, -sq * q0.z),
                                    fmaf(cq, p0.w, -sq * q0.w));
                Qp[1] = make_float4(fmaf(cq, p1.x, -sq * q1.x),
                                    fmaf(cq, p1.y, -sq * q1.y),
                                    fmaf(cq, p1.z, -sq * q1.z),
                                    fmaf(cq, p1.w, -sq * q1.w));
                Qq[0] = make_float4(fmaf(sq, p0.x, cq * q0.x),
                                    fmaf(sq, p0.y, cq * q0.y),
                                    fmaf(sq, p0.z, cq * q0.z),
                                    fmaf(sq, p0.w, cq * q0.w));
                Qq[1] = make_float4(fmaf(sq, p1.x, cq * q1.x),
                                    fmaf(sq, p1.y, cq * q1.y),
                                    fmaf(sq, p1.z, cq * q1.z),
                                    fmaf(sq, p1.w, cq * q1.w));
            }

            // ---- advance indices (+1 mod 63; lane 0 keeps pl = 63) ----
            if (lane) {
                pl  = (pl  == 62)       ? 0 : pl + 1;
                plS = (plS == 62 * STR) ? 0 : plS + STR;
            }
            ql  = (ql  == 62)       ? 0 : ql + 1;
            qlS = (qlS == 62 * STR) ? 0 : qlS + STR;

            __syncthreads();
            float* t = Ac; Ac = An; An = t;
        }
    }

    // =======================================================================
    // 2nd-order Daleckii-Krein sqrt of A = D + E:
    //   F_ij = g_i d_ij + E_ij g[d_i,d_j]                 (1st order)
    //   S_ij = (G_ij - G_ji)/(d_i - d_j),  G = F_off * E  (2nd order, i!=j)
    //   S_ii = sum_k E_ik^2 * g[d_i,d_k,d_i]              (2nd order diag)
    //   msqrt = Qt^T (F + S) Qt
    // =======================================================================

    __syncthreads();
    if (tid < DIM) {
        const float lam = Ac[tid * STR + tid];
        dsv[tid] = lam;
        gs[tid] = copysignf(sqrtf(fabsf(lam)), lam);
    }
    __syncthreads();

    // ---- build F into An ----
    {
        const int i = tid >> 2;
        const int j0 = (tid & 3) * 16;
        const float gi = gs[i];
        const float di = dsv[i];
#pragma unroll
        for (int u = 0; u < 16; u++) {
            const int j = j0 + u;
            const float gj = gs[j];
            float DD;
            if ((__float_as_int(gi) ^ __float_as_int(gj)) >= 0) {
                DD = __fdividef(1.f, fabsf(gi) + fabsf(gj) + 1e-12f);
            } else {
                const float den = di - dsv[j];
                DD = __fdividef(gi - gj, den + copysignf(1e-12f, den));
            }
            An[i * STR + j] = (i == j) ? gi : Ac[i * STR + j] * DD;
        }
    }
    __syncthreads();

    // ---- GEMM: G = F_off * E  (4x4 register tile) ----
    const int i0  = (tid >> 4) * 4;
    const int j0g = (tid & 15) * 4;
    {
        float4 acc[4];
#pragma unroll
        for (int r = 0; r < 4; r++) acc[r] = make_float4(0.f, 0.f, 0.f, 0.f);
#pragma unroll 4
        for (int k = 0; k < DIM; k++) {
            const float4 e4 = *(const float4*)&Ac[k * STR + j0g];
#pragma unroll
            for (int r = 0; r < 4; r++) {
                const float bk = An[(i0 + r) * STR + k];
                acc[r].x = fmaf(bk, e4.x, acc[r].x);
                acc[r].y = fmaf(bk, e4.y, acc[r].y);
                acc[r].z = fmaf(bk, e4.z, acc[r].z);
                acc[r].w = fmaf(bk, e4.w, acc[r].w);
            }
        }
        // fix k==i term (F diag is g_i, not part of F_off): acc -= g_i * A[i][j]
        // fix k==j term (A diag is d_j, not part of E):      acc -= B_ij * d_j
#pragma unroll
        for (int r = 0; r < 4; r++) {
            const int i = i0 + r;
            const float gi = gs[i];
            const float4 arow = *(const float4*)&Ac[i * STR + j0g];
            acc[r].x -= gi * arow.x; acc[r].y -= gi * arow.y;
            acc[r].z -= gi * arow.z; acc[r].w -= gi * arow.w;
            float bv[4];
#pragma unroll
            for (int cc = 0; cc < 4; cc++) {
                const int j = j0g + cc;
                bv[cc] = (i == j) ? 0.f : An[i * STR + j];
            }
            acc[r].x -= bv[0] * dsv[j0g + 0];
            acc[r].y -= bv[1] * dsv[j0g + 1];
            acc[r].z -= bv[2] * dsv[j0g + 2];
            acc[r].w -= bv[3] * dsv[j0g + 3];
            *(float4*)&Gbuf[i * STR + j0g] = acc[r];
        }
    }
    __syncthreads();

    // ---- S: off-diagonal correction into An ----
    {
#pragma unroll
        for (int r = 0; r < 4; r++) {
            const int i = i0 + r;
            const float di = dsv[i];
#pragma unroll
            for (int cc = 0; cc < 4; cc++) {
                const int j = j0g + cc;
                if (i == j) continue;
                const float num = Gbuf[i * STR + j] - Gbuf[j * STR + i];
                const float den = di - dsv[j];
                const float ad = fabsf(den);
                float S = 0.f;
                if (ad > 1e-3f * (fabsf(di) + fabsf(dsv[j]))) {
                    S = __fdividef(num, den);
                }
                An[i * STR + j] += S;
            }
        }
    }
    // ---- S: diagonal correction (thread group of 4 per row) ----
    {
        const int i = tid >> 2;
        const int k0 = (tid & 3) * 16;
        const float di = dsv[i];
        const float agi = fabsf(gs[i]);
        float ssum = 0.f;
#pragma unroll 4
        for (int kk = k0; kk < k0 + 16; kk++) {
            if (kk == i) continue;
            const float e = Ac[i * STR + kk];
            const float dk = dsv[kk];
            const float agk = fabsf(gs[kk]);
            float w;
            if ((__float_as_int(di) ^ __float_as_int(dk)) >= 0) {
                const float t = agi + agk;
                w = -copysignf(__fdividef(1.f, 2.f * agi * t * t + 1e-20f), di);
            } else {
                const float den = di - dk;
                const float gij = __fdividef(gs[i] - gs[kk],
                                             den + copysignf(1e-20f, den));
                w = __fdividef(__fdividef(0.5f, agi + 1e-20f) - gij,
                               den + copysignf(1e-20f, den));
            }
            ssum = fmaf(e * e, w, ssum);
        }
        ssum += __shfl_xor_sync(0xffffffffu, ssum, 1);
        ssum += __shfl_xor_sync(0xffffffffu, ssum, 2);
        if ((tid & 3) == 0) An[i * STR + i] += ssum;
    }
    __syncthreads();

    // ---- GEMM1: T = F2 * Qt  -> Ac ----
    {
        float4 acc[4];
#pragma unroll
        for (int r = 0; r < 4; r++) acc[r] = make_float4(0.f, 0.f, 0.f, 0.f);
#pragma unroll 4
        for (int l = 0; l < DIM; l++) {
            const float4 q4 = *(const float4*)&Qts[l * STR + j0g];
#pragma unroll
            for (int r = 0; r < 4; r++) {
                const float fv = An[(i0 + r) * STR + l];
                acc[r].x = fmaf(fv, q4.x, acc[r].x);
                acc[r].y = fmaf(fv, q4.y, acc[r].y);
                acc[r].z = fmaf(fv, q4.z, acc[r].z);
                acc[r].w = fmaf(fv, q4.w, acc[r].w);
            }
        }
        __syncthreads();   // all reads of Ac (E) done before overwrite
#pragma unroll
        for (int r = 0; r < 4; r++)
            *(float4*)&Ac[(i0 + r) * STR + j0g] = acc[r];
    }
    __syncthreads();

    // ---- GEMM2: R = Qt^T * T; L2 normalize; write out ----
    {
        float4 acc[4];
#pragma unroll
        for (int r = 0; r < 4; r++) acc[r] = make_float4(0.f, 0.f, 0.f, 0.f);
#pragma unroll 4
        for (int k = 0; k < DIM; k++) {
            const float4 t4 = *(const float4*)&Ac[k * STR + j0g];
#pragma unroll
            for (int r = 0; r < 4; r++) {
                const float qv = Qts[k * STR + i0 + r];
                acc[r].x = fmaf(qv, t4.x, acc[r].x);
                acc[r].y = fmaf(qv, t4.y, acc[r].y);
                acc[r].z = fmaf(qv, t4.z, acc[r].z);
                acc[r].w = fmaf(qv, t4.w, acc[r].w);
            }
        }
        float ssq = 0.f;
#pragma unroll
        for (int r = 0; r < 4; r++)
            ssq += acc[r].x*acc[r].x + acc[r].y*acc[r].y
                 + acc[r].z*acc[r].z + acc[r].w*acc[r].w;
        const float total = block_reduce_sum(ssq, red, tid);
        const float scale = 1.f / fmaxf(sqrtf(total), 1e-12f);
#pragma unroll
        for (int r = 0; r < 4; r++) {
            acc[r].x *= scale; acc[r].y *= scale;
            acc[r].z *= scale; acc[r].w *= scale;
            *(float4*)(out + (size_t)b * (DIM * DIM) + (i0 + r) * DIM + j0g) = acc[r];
        }
    }
}

// ---------------------------------------------------------------------------
extern "C" void kernel_launch(void* const* d_in, const int* in_sizes, int n_in,
                              void* d_out, int out_size) {
    const float* x = (const float*)d_in[0];
    float* out = (float*)d_out;

    cudaFuncSetAttribute(sop_eig_kernel,
                         cudaFuncAttributeMaxDynamicSharedMemorySize,
                         EIG_SMEM_BYTES);

    sop_partial_max<<<dim3(SPLIT, BATCH), 256>>>(x);
    sop_eig_kernel<<<BATCH, ETHREADS, EIG_SMEM_BYTES>>>(out);
}

// round 8
// speedup vs baseline: 1.1537x; 1.1537x over previous
#include <cuda_runtime.h>
#include <math.h>
#include <float.h>

#define BATCH 16
#define NPTS  2048
#define DIM   64
#define SPLIT 8                  // chunks per batch (kernel1 grid.x)
#define GROUPS 4                 // tile-groups per CTA
#define SPLIT_EFF (SPLIT * GROUPS)   // 32 partials per batch
#define CHUNK (NPTS / SPLIT)     // 256 rows per CTA
#define GROWS (CHUNK / GROUPS)   // 64 rows per group
#define STR 68                   // smem row stride: 16B-aligned rows
#define ETHREADS 512

#define EIG_SMEM_FLOATS (4 * DIM * STR)
#define EIG_SMEM_BYTES  (EIG_SMEM_FLOATS * 4)
#define PM_SMEM_BYTES   (CHUNK * DIM * 4)   // 64 KB

// scratch for partial maxima: 16 * 32 * 4096 * 4B = 8 MB
__device__ float g_partial[BATCH][SPLIT_EFF][DIM * DIM];

// ---------------------------------------------------------------------------
// Kernel 1: partial max of outer products. grid=(SPLIT,BATCH), 256 threads.
// 4 groups of 64 threads; each group: 64 n-rows, 8x8 register tile/thread.
// ---------------------------------------------------------------------------
__global__ void __launch_bounds__(256) sop_partial_max(const float* __restrict__ x) {
    extern __shared__ float xs[];   // [CHUNK][DIM]
    const int b = blockIdx.y;
    const int c = blockIdx.x;
    const int tid = threadIdx.x;

    const float* xp = x + ((size_t)b * NPTS + (size_t)c * CHUNK) * DIM;
    for (int e = tid * 4; e < CHUNK * DIM; e += 256 * 4) {
        float4 v = *(const float4*)(xp + e);
        *(float4*)(xs + e) = v;
    }
    __syncthreads();

    const int g  = tid >> 6;          // group 0..3
    const int gt = tid & 63;
    const int ti = (gt >> 3) * 8;
    const int tj = (gt & 7) * 8;
    const float* base = xs + g * GROWS * DIM;

    float acc[8][8];
#pragma unroll
    for (int a = 0; a < 8; a++)
#pragma unroll
        for (int bb = 0; bb < 8; bb++) acc[a][bb] = -FLT_MAX;

    for (int n = 0; n < GROWS; n++) {
        const float4 vi0 = *(const float4*)&base[n * DIM + ti];
        const float4 vi1 = *(const float4*)&base[n * DIM + ti + 4];
        const float4 vj0 = *(const float4*)&base[n * DIM + tj];
        const float4 vj1 = *(const float4*)&base[n * DIM + tj + 4];
        const float fi[8] = {vi0.x, vi0.y, vi0.z, vi0.w, vi1.x, vi1.y, vi1.z, vi1.w};
        const float fj[8] = {vj0.x, vj0.y, vj0.z, vj0.w, vj1.x, vj1.y, vj1.z, vj1.w};
#pragma unroll
        for (int a = 0; a < 8; a++)
#pragma unroll
            for (int bb = 0; bb < 8; bb++)
                acc[a][bb] = fmaxf(acc[a][bb], fi[a] * fj[bb]);
    }

    float* outp = g_partial[b][c * GROUPS + g];
#pragma unroll
    for (int a = 0; a < 8; a++) {
        *(float4*)(outp + (ti + a) * DIM + tj) =
            make_float4(acc[a][0], acc[a][1], acc[a][2], acc[a][3]);
        *(float4*)(outp + (ti + a) * DIM + tj + 4) =
            make_float4(acc[a][4], acc[a][5], acc[a][6], acc[a][7]);
    }
}

// ---------------------------------------------------------------------------
// block reduce sum for 512 threads / 16 warps
// ---------------------------------------------------------------------------
__device__ __forceinline__ float block_reduce_sum(float v, float* red, int tid) {
    __syncthreads();
#pragma unroll
    for (int o = 16; o; o >>= 1) v += __shfl_down_sync(0xffffffffu, v, o);
    if ((tid & 31) == 0) red[tid >> 5] = v;
    __syncthreads();
    if (tid < 32) {
        float w = (tid < 16) ? red[tid] : 0.f;
#pragma unroll
        for (int o = 8; o; o >>= 1) w += __shfl_down_sync(0xffffffffu, w, o);
        if (tid == 0) red[0] = w;
    }
    __syncthreads();
    return red[0];
}

// ---------------------------------------------------------------------------
// Kernel 2: 4 Jacobi sweeps (+valve 5th), 2nd-order Daleckii-Krein sqrt,
// Qt^T F2 Qt reconstruction, L2 normalize. 512 threads / 16 warps.
// Warp w owns row-pairs {w, w+16} (incremental offset registers);
// lane j owns column pair j. Qt update: half-warp float4.
// ---------------------------------------------------------------------------
__global__ void __launch_bounds__(ETHREADS) sop_eig_kernel(float* __restrict__ out) {
    extern __shared__ float dsm[];
    float* Abuf0 = dsm;
    float* Abuf1 = dsm + DIM * STR;
    float* Qts   = dsm + 2 * DIM * STR;
    float* Gbuf  = dsm + 3 * DIM * STR;

    __shared__ float red[16];
    __shared__ float gs[DIM];
    __shared__ float dsv[DIM];

    const int b = blockIdx.x;
    const int tid = threadIdx.x;
    const int warp = tid >> 5;
    const int lane = tid & 31;

    // ---- reduce partials into A0 (float4), init Qt = I ----
    float frloc = 0.f;
    {
        const int e0 = tid * 8;
        const int i = e0 >> 6, j0 = e0 & 63;
        float4 m0 = make_float4(-FLT_MAX, -FLT_MAX, -FLT_MAX, -FLT_MAX);
        float4 m1 = m0;
#pragma unroll 8
        for (int c = 0; c < SPLIT_EFF; c++) {
            const float4* gp = (const float4*)&g_partial[b][c][e0];
            float4 v0 = gp[0], v1 = gp[1];
            m0.x = fmaxf(m0.x, v0.x); m0.y = fmaxf(m0.y, v0.y);
            m0.z = fmaxf(m0.z, v0.z); m0.w = fmaxf(m0.w, v0.w);
            m1.x = fmaxf(m1.x, v1.x); m1.y = fmaxf(m1.y, v1.y);
            m1.z = fmaxf(m1.z, v1.z); m1.w = fmaxf(m1.w, v1.w);
        }
        *(float4*)&Abuf0[i * STR + j0]     = m0;
        *(float4*)&Abuf0[i * STR + j0 + 4] = m1;
        frloc = m0.x*m0.x + m0.y*m0.y + m0.z*m0.z + m0.w*m0.w
              + m1.x*m1.x + m1.y*m1.y + m1.z*m1.z + m1.w*m1.w;
        float4 id0 = make_float4((i == j0+0)?1.f:0.f, (i == j0+1)?1.f:0.f,
                                 (i == j0+2)?1.f:0.f, (i == j0+3)?1.f:0.f);
        float4 id1 = make_float4((i == j0+4)?1.f:0.f, (i == j0+5)?1.f:0.f,
                                 (i == j0+6)?1.f:0.f, (i == j0+7)?1.f:0.f);
        *(float4*)&Qts[i * STR + j0]     = id0;
        *(float4*)&Qts[i * STR + j0 + 4] = id1;
    }
    const float frob2 = block_reduce_sum(frloc, red, tid) + 1e-30f;

    // ---- persistent tournament indices ----
    // lane's column pair:
    int pl, ql;
    if (lane == 0) { pl = 63; ql = 0; }
    else           { pl = lane; ql = 63 - lane; }
    int plS = pl * STR;
    int qlS = ql * STR;
    // warp's row-pair offsets (A: pair index warp, B: pair index warp+16)
    int pSA, qSA, pSB, qSB;
    if (warp == 0) { pSA = 63 * STR; qSA = 0; }
    else           { pSA = warp * STR; qSA = (63 - warp) * STR; }
    pSB = (warp + 16) * STR;
    qSB = (47 - warp) * STR;

    float* Ac = Abuf0;
    float* An = Abuf1;

    for (int sweep = 0; sweep < 5; sweep++) {
        if (sweep == 4) {   // valve: 5th sweep only if off-diag too big for DK2
            float off = 0.f;
            const int e0 = tid * 8;
            const int i = e0 >> 6, j0 = e0 & 63;
#pragma unroll
            for (int u = 0; u < 8; u++) {
                const float v = Ac[i * STR + j0 + u];
                off += (i != j0 + u) ? v * v : 0.f;
            }
            const float offt = block_reduce_sum(off, red, tid);
            if (offt < 3e-5f * frob2) break;
        }

        for (int r = 0; r < 63; r++) {
            // ---- rotation params for column pair 'lane' (2 MUFU) ----
            const float app = Ac[plS + pl];
            const float aqq = Ac[qlS + ql];
            const float apq = Ac[plS + ql];
            const float d = aqq - app;
            const float g = apq + apq;
            const float rr = fmaf(d, d, g * g);
            const float ir = __frsqrt_rn(rr);
            const float xv = fabsf(d) * ir;
            const float yv = fmaf(0.5f, xv, 0.5f);
            const float ic = __frsqrt_rn(yv);
            float c = yv * ic;
            float s = 0.5f * g * ir * ic;
            s = __int_as_float(__float_as_int(s) ^
                               (__float_as_int(d) & 0x80000000));
            if (rr < 1e-40f) { c = 1.f; s = 0.f; }

            // ---- row-pair params: only c,s via shfl (offsets are registers) --
            const float cA = __shfl_sync(0xffffffffu, c, warp);
            const float sA = __shfl_sync(0xffffffffu, s, warp);
            const float cB = __shfl_sync(0xffffffffu, c, warp + 16);
            const float sB = __shfl_sync(0xffffffffu, s, warp + 16);

            // ---- A: fused two-sided 2x2 update, row-pair A ----
            {
                const float a_pp = Ac[pSA + pl];
                const float a_pq = Ac[pSA + ql];
                const float a_qp = Ac[qSA + pl];
                const float a_qq = Ac[qSA + ql];
                const float rp_p = fmaf(cA, a_pp, -sA * a_qp);
                const float rp_q = fmaf(cA, a_pq, -sA * a_qq);
                const float rq_p = fmaf(sA, a_pp,  cA * a_qp);
                const float rq_q = fmaf(sA, a_pq,  cA * a_qq);
                An[pSA + pl] = fmaf(c, rp_p, -s * rp_q);
                An[pSA + ql] = fmaf(s, rp_p,  c * rp_q);
                An[qSA + pl] = fmaf(c, rq_p, -s * rq_q);
                An[qSA + ql] = fmaf(s, rq_p,  c * rq_q);
            }
            // ---- A: row-pair B ----
            {
                const float a_pp = Ac[pSB + pl];
                const float a_pq = Ac[pSB + ql];
                const float a_qp = Ac[qSB + pl];
                const float a_qq = Ac[qSB + ql];
                const float rp_p = fmaf(cB, a_pp, -sB * a_qp);
                const float rp_q = fmaf(cB, a_pq, -sB * a_qq);
                const float rq_p = fmaf(sB, a_pp,  cB * a_qp);
                const float rq_q = fmaf(sB, a_pq,  cB * a_qq);
                An[pSB + pl] = fmaf(c, rp_p, -s * rp_q);
                An[pSB + ql] = fmaf(s, rp_p,  c * rp_q);
                An[qSB + pl] = fmaf(c, rq_p, -s * rq_q);
                An[qSB + ql] = fmaf(s, rq_p,  c * rq_q);
            }

            // ---- Qt <- J^T Qt: half-warp float4 ----
            {
                const float cq = (lane < 16) ? cA : cB;
                const float sq = (lane < 16) ? sA : sB;
                const int   pS = (lane < 16) ? pSA : pSB;
                const int   qS = (lane < 16) ? qSA : qSB;
                const int   sub = (lane & 15) * 4;
                float4* Qp = (float4*)(Qts + pS + sub);
                float4* Qq = (float4*)(Qts + qS + sub);
                const float4 qp = *Qp;
                const float4 qq = *Qq;
                *Qp = make_float4(fmaf(cq, qp.x, -sq * qq.x),
                                  fmaf(cq, qp.y, -sq * qq.y),
                                  fmaf(cq, qp.z, -sq * qq.z),
                                  fmaf(cq, qp.w, -sq * qq.w));
                *Qq = make_float4(fmaf(sq, qp.x, cq * qq.x),
                                  fmaf(sq, qp.y, cq * qq.y),
                                  fmaf(sq, qp.z, cq * qq.z),
                                  fmaf(sq, qp.w, cq * qq.w));
            }

            // ---- advance all indices (+1 mod 63; pair-0 keeps p = 63) ----
            if (lane) {
                pl  = (pl  == 62)       ? 0 : pl + 1;
                plS = (plS == 62 * STR) ? 0 : plS + STR;
            }
            ql  = (ql  == 62)       ? 0 : ql + 1;
            qlS = (qlS == 62 * STR) ? 0 : qlS + STR;
            if (warp) pSA = (pSA == 62 * STR) ? 0 : pSA + STR;
            qSA = (qSA == 62 * STR) ? 0 : qSA + STR;
            pSB = (pSB == 62 * STR) ? 0 : pSB + STR;
            qSB = (qSB == 62 * STR) ? 0 : qSB + STR;

            __syncthreads();
            float* t = Ac; Ac = An; An = t;
        }
    }

    // =======================================================================
    // 2nd-order Daleckii-Krein sqrt of A = D + E, msqrt = Qt^T (F+S) Qt
    // =======================================================================

    __syncthreads();
    if (tid < DIM) {
        const float lam = Ac[tid * STR + tid];
        dsv[tid] = lam;
        gs[tid] = copysignf(sqrtf(fabsf(lam)), lam);
    }
    __syncthreads();

    // ---- build F into An (thread: row i, 8 cols) ----
    {
        const int i = tid >> 3;
        const int j0 = (tid & 7) * 8;
        const float gi = gs[i];
        const float di = dsv[i];
#pragma unroll
        for (int u = 0; u < 8; u++) {
            const int j = j0 + u;
            const float gj = gs[j];
            float DD;
            if ((__float_as_int(gi) ^ __float_as_int(gj)) >= 0) {
                DD = __fdividef(1.f, fabsf(gi) + fabsf(gj) + 1e-12f);
            } else {
                const float den = di - dsv[j];
                DD = __fdividef(gi - gj, den + copysignf(1e-12f, den));
            }
            An[i * STR + j] = (i == j) ? gi : Ac[i * STR + j] * DD;
        }
    }
    __syncthreads();

    // ---- GEMM: G = F_off * E  (2x4 register tile) ----
    const int i0  = (tid >> 4) * 2;
    const int j0g = (tid & 15) * 4;
    {
        float4 acc[2];
#pragma unroll
        for (int r = 0; r < 2; r++) acc[r] = make_float4(0.f, 0.f, 0.f, 0.f);
#pragma unroll 4
        for (int k = 0; k < DIM; k++) {
            const float4 e4 = *(const float4*)&Ac[k * STR + j0g];
#pragma unroll
            for (int r = 0; r < 2; r++) {
                const float bk = An[(i0 + r) * STR + k];
                acc[r].x = fmaf(bk, e4.x, acc[r].x);
                acc[r].y = fmaf(bk, e4.y, acc[r].y);
                acc[r].z = fmaf(bk, e4.z, acc[r].z);
                acc[r].w = fmaf(bk, e4.w, acc[r].w);
            }
        }
        // remove k==i (F diag) and k==j (A diag) contributions
#pragma unroll
        for (int r = 0; r < 2; r++) {
            const int i = i0 + r;
            const float gi = gs[i];
            const float4 arow = *(const float4*)&Ac[i * STR + j0g];
            acc[r].x -= gi * arow.x; acc[r].y -= gi * arow.y;
            acc[r].z -= gi * arow.z; acc[r].w -= gi * arow.w;
            float bv[4];
#pragma unroll
            for (int cc = 0; cc < 4; cc++) {
                const int j = j0g + cc;
                bv[cc] = (i == j) ? 0.f : An[i * STR + j];
            }
            acc[r].x -= bv[0] * dsv[j0g + 0];
            acc[r].y -= bv[1] * dsv[j0g + 1];
            acc[r].z -= bv[2] * dsv[j0g + 2];
            acc[r].w -= bv[3] * dsv[j0g + 3];
            *(float4*)&Gbuf[i * STR + j0g] = acc[r];
        }
    }
    __syncthreads();

    // ---- S: off-diagonal correction into An ----
    {
#pragma unroll
        for (int r = 0; r < 2; r++) {
            const int i = i0 + r;
            const float di = dsv[i];
#pragma unroll
            for (int cc = 0; cc < 4; cc++) {
                const int j = j0g + cc;
                if (i == j) continue;
                const float num = Gbuf[i * STR + j] - Gbuf[j * STR + i];
                const float den = di - dsv[j];
                float S = 0.f;
                if (fabsf(den) > 1e-3f * (fabsf(di) + fabsf(dsv[j]))) {
                    S = __fdividef(num, den);
                }
                An[i * STR + j] += S;
            }
        }
    }
    // ---- S: diagonal correction (8 threads per row) ----
    {
        const int i = tid >> 3;
        const int k0 = (tid & 7) * 8;
        const float di = dsv[i];
        const float agi = fabsf(gs[i]);
        float ssum = 0.f;
#pragma unroll
        for (int kk = k0; kk < k0 + 8; kk++) {
            if (kk == i) continue;
            const float e = Ac[i * STR + kk];
            const float dk = dsv[kk];
            const float agk = fabsf(gs[kk]);
            float w;
            if ((__float_as_int(di) ^ __float_as_int(dk)) >= 0) {
                const float t = agi + agk;
                w = -copysignf(__fdividef(1.f, 2.f * agi * t * t + 1e-20f), di);
            } else {
                const float den = di - dk;
                const float gij = __fdividef(gs[i] - gs[kk],
                                             den + copysignf(1e-20f, den));
                w = __fdividef(__fdividef(0.5f, agi + 1e-20f) - gij,
                               den + copysignf(1e-20f, den));
            }
            ssum = fmaf(e * e, w, ssum);
        }
        ssum += __shfl_xor_sync(0xffffffffu, ssum, 1);
        ssum += __shfl_xor_sync(0xffffffffu, ssum, 2);
        ssum += __shfl_xor_sync(0xffffffffu, ssum, 4);
        if ((tid & 7) == 0) An[i * STR + i] += ssum;
    }
    __syncthreads();

    // ---- GEMM1: T = F2 * Qt  -> Ac ----
    {
        float4 acc[2];
#pragma unroll
        for (int r = 0; r < 2; r++) acc[r] = make_float4(0.f, 0.f, 0.f, 0.f);
#pragma unroll 4
        for (int l = 0; l < DIM; l++) {
            const float4 q4 = *(const float4*)&Qts[l * STR + j0g];
#pragma unroll
            for (int r = 0; r < 2; r++) {
                const float fv = An[(i0 + r) * STR + l];
                acc[r].x = fmaf(fv, q4.x, acc[r].x);
                acc[r].y = fmaf(fv, q4.y, acc[r].y);
                acc[r].z = fmaf(fv, q4.z, acc[r].z);
                acc[r].w = fmaf(fv, q4.w, acc[r].w);
            }
        }
        __syncthreads();
#pragma unroll
        for (int r = 0; r < 2; r++)
            *(float4*)&Ac[(i0 + r) * STR + j0g] = acc[r];
    }
    __syncthreads();

    // ---- GEMM2: R = Qt^T * T; L2 normalize; write out ----
    {
        float4 acc[2];
#pragma unroll
        for (int r = 0; r < 2; r++) acc[r] = make_float4(0.f, 0.f, 0.f, 0.f);
#pragma unroll 4
        for (int k = 0; k < DIM; k++) {
            const float4 t4 = *(const float4*)&Ac[k * STR + j0g];
#pragma unroll
            for (int r = 0; r < 2; r++) {
                const float qv = Qts[k * STR + i0 + r];
                acc[r].x = fmaf(qv, t4.x, acc[r].x);
                acc[r].y = fmaf(qv, t4.y, acc[r].y);
                acc[r].z = fmaf(qv, t4.z, acc[r].z);
                acc[r].w = fmaf(qv, t4.w, acc[r].w);
            }
        }
        float ssq = 0.f;
#pragma unroll
        for (int r = 0; r < 2; r++)
            ssq += acc[r].x*acc[r].x + acc[r].y*acc[r].y
                 + acc[r].z*acc[r].z + acc[r].w*acc[r].w;
        const float total = block_reduce_sum(ssq, red, tid);
        const float scale = 1.f / fmaxf(sqrtf(total), 1e-12f);
#pragma unroll
        for (int r = 0; r < 2; r++) {
            acc[r].x *= scale; acc[r].y *= scale;
            acc[r].z *= scale; acc[r].w *= scale;
            *(float4*)(out + (size_t)b * (DIM * DIM) + (i0 + r) * DIM + j0g) = acc[r];
        }
    }
}

// ---------------------------------------------------------------------------
extern "C" void kernel_launch(void* const* d_in, const int* in_sizes, int n_in,
                              void* d_out, int out_size) {
    const float* x = (const float*)d_in[0];
    float* out = (float*)d_out;

    cudaFuncSetAttribute(sop_partial_max,
                         cudaFuncAttributeMaxDynamicSharedMemorySize,
                         PM_SMEM_BYTES);
    cudaFuncSetAttribute(sop_eig_kernel,
                         cudaFuncAttributeMaxDynamicSharedMemorySize,
                         EIG_SMEM_BYTES);

    sop_partial_max<<<dim3(SPLIT, BATCH), 256, PM_SMEM_BYTES>>>(x);
    sop_eig_kernel<<<BATCH, ETHREADS, EIG_SMEM_BYTES>>>(out);
}